// round 9
// baseline (speedup 1.0000x reference)
#include <cuda_runtime.h>
#include <math.h>
#include <stdint.h>

#define BATCH 2
#define SEQ   2048
#define DMODEL 1024
#define HEADS 16
#define HD    64
#define QKV_N (3*DMODEL)       // 3072
#define MROWS (BATCH*SEQ)      // 4096

__device__ float g_qkv[(size_t)MROWS * QKV_N];    // [B*S, 3072]
__device__ float g_att[(size_t)MROWS * DMODEL];   // [B*S, 1024]

// ===========================================================================
// helpers
// ===========================================================================
__device__ __forceinline__ float f2tf32(float f) {
    uint32_t r;
    asm("cvt.rna.tf32.f32 %0, %1;" : "=r"(r) : "f"(f));
    return __uint_as_float(r);
}
__device__ __forceinline__ uint32_t tf32bits(float f) {
    uint32_t r;
    asm("cvt.rna.tf32.f32 %0, %1;" : "=r"(r) : "f"(f));
    return r;
}
__device__ __forceinline__ uint32_t smem_u32(const void* p) {
    uint32_t a;
    asm("{ .reg .u64 t; cvta.to.shared.u64 t, %1; cvt.u32.u64 %0, t; }" : "=r"(a) : "l"(p));
    return a;
}
__device__ __forceinline__ void mma_tf32(float c[4], const uint32_t a[4], const uint32_t b[2]) {
    asm volatile(
        "mma.sync.aligned.m16n8k8.row.col.f32.tf32.tf32.f32 "
        "{%0,%1,%2,%3}, {%4,%5,%6,%7}, {%8,%9}, {%0,%1,%2,%3};"
        : "+f"(c[0]), "+f"(c[1]), "+f"(c[2]), "+f"(c[3])
        : "r"(a[0]), "r"(a[1]), "r"(a[2]), "r"(a[3]), "r"(b[0]), "r"(b[1]));
}
__device__ __forceinline__ void cp_async16(uint32_t saddr, const void* gptr) {
    asm volatile("cp.async.ca.shared.global [%0], [%1], 16;" :: "r"(saddr), "l"(gptr));
}
__device__ __forceinline__ void cp_commit() {
    asm volatile("cp.async.commit_group;" ::: "memory");
}
__device__ __forceinline__ void cp_wait0() {
    asm volatile("cp.async.wait_group 0;" ::: "memory");
}
__device__ __forceinline__ void cp_wait2() {
    asm volatile("cp.async.wait_group 2;" ::: "memory");
}

// ===========================================================================
// tf32 mma.sync GEMM + bias, 4-stage cp.async pipeline (unchanged from R6).
// ===========================================================================
#define AS_P 20
#define BS_P 136
#define AS_FLOATS (128 * AS_P)
#define BS_FLOATS (16 * BS_P)
#define ST_FLOATS (AS_FLOATS + BS_FLOATS)
#define NSTAGE 4
#define GEMM_SMEM (NSTAGE * ST_FLOATS * sizeof(float))   // 75776

__global__ __launch_bounds__(256, 2)
void gemm_mma_kernel(const float* __restrict__ A, const float* __restrict__ W,
                     const float* __restrict__ bias, float* __restrict__ C,
                     int N, int K)
{
    extern __shared__ float smf[];
    const uint32_t smb = smem_u32(smf);

    const int t    = threadIdx.x;
    const int lane = t & 31;
    const int wid  = t >> 5;
    const int wm   = (wid >> 2) * 64;
    const int wn   = (wid & 3) * 32;
    const int g    = lane >> 2;
    const int t4   = lane & 3;
    const int m0   = blockIdx.y * 128;
    const int n0   = blockIdx.x * 128;

    const int ar = t >> 1;
    const int as0 = (t & 1) * 2;
    const int br = t >> 4;
    const int bs0 = (t & 15) * 2;

    float acc[4][4][4];
#pragma unroll
    for (int mi = 0; mi < 4; mi++)
#pragma unroll
        for (int ni = 0; ni < 4; ni++)
#pragma unroll
            for (int r = 0; r < 4; r++) acc[mi][ni][r] = 0.f;

    const int nch = K / 16;

    auto load_chunk = [&](int c, int s) {
        const uint32_t stA = smb + (uint32_t)(s * ST_FLOATS) * 4u;
        const uint32_t stB = stA + (uint32_t)AS_FLOATS * 4u;
        const float* Ab = A + (size_t)(m0 + ar) * K + c * 16 + as0 * 4;
        cp_async16(stA + (uint32_t)(ar * AS_P + as0 * 4) * 4u, Ab);
        cp_async16(stA + (uint32_t)(ar * AS_P + (as0 + 1) * 4) * 4u, Ab + 4);
        const float* Wb = W + (size_t)(c * 16 + br) * N + n0 + bs0 * 4;
        cp_async16(stB + (uint32_t)(br * BS_P + bs0 * 4) * 4u, Wb);
        cp_async16(stB + (uint32_t)(br * BS_P + (bs0 + 1) * 4) * 4u, Wb + 4);
    };

#pragma unroll
    for (int c = 0; c < NSTAGE - 1; c++) { load_chunk(c, c); cp_commit(); }

    for (int c = 0; c < nch; c++) {
        cp_wait2();
        __syncthreads();

        if (c + NSTAGE - 1 < nch) load_chunk(c + NSTAGE - 1, (c + NSTAGE - 1) & (NSTAGE - 1));
        cp_commit();

        const int s = c & (NSTAGE - 1);
        const float* as_ = smf + s * ST_FLOATS;
        const float* bs_ = as_ + AS_FLOATS;

#pragma unroll
        for (int ks = 0; ks < 2; ks++) {
            const int kk = ks * 8;
            uint32_t af[4][4], bf[4][2];
#pragma unroll
            for (int mi = 0; mi < 4; mi++) {
                int r0 = wm + mi * 16 + g;
                af[mi][0] = tf32bits(as_[r0 * AS_P + kk + t4]);
                af[mi][1] = tf32bits(as_[(r0 + 8) * AS_P + kk + t4]);
                af[mi][2] = tf32bits(as_[r0 * AS_P + kk + t4 + 4]);
                af[mi][3] = tf32bits(as_[(r0 + 8) * AS_P + kk + t4 + 4]);
            }
#pragma unroll
            for (int ni = 0; ni < 4; ni++) {
                int cc = wn + ni * 8 + g;
                bf[ni][0] = tf32bits(bs_[(kk + t4) * BS_P + cc]);
                bf[ni][1] = tf32bits(bs_[(kk + t4 + 4) * BS_P + cc]);
            }
#pragma unroll
            for (int mi = 0; mi < 4; mi++)
#pragma unroll
                for (int ni = 0; ni < 4; ni++)
                    mma_tf32(acc[mi][ni], af[mi], bf[ni]);
        }
    }

#pragma unroll
    for (int mi = 0; mi < 4; mi++) {
        int row = m0 + wm + mi * 16 + g;
#pragma unroll
        for (int ni = 0; ni < 4; ni++) {
            int col = n0 + wn + ni * 8 + 2 * t4;
            float2 bv = *(const float2*)(bias + col);
            float2 v0 = make_float2(acc[mi][ni][0] + bv.x, acc[mi][ni][1] + bv.y);
            float2 v1 = make_float2(acc[mi][ni][2] + bv.x, acc[mi][ni][3] + bv.y);
            *(float2*)(C + (size_t)row * N + col)       = v0;
            *(float2*)(C + (size_t)(row + 8) * N + col) = v1;
        }
    }
}

// ===========================================================================
// tf32 mma.sync flash attention.
// cp.async double-buffered K/V + in-smem tf32 conversion pass; Q in regs.
// K pitch 68 (row access conflict-free), V pitch 72 (col access conflict-free:
// bank = 8*t4 + g + C, all 32 distinct). No V transpose needed.
// ===========================================================================
#define KP 68
#define VP 72
#define KV_K (64*KP)                // 4352 floats
#define KV_V (64*VP)                // 4608 floats
#define STG_F (KV_K + KV_V)         // floats per stage
#define PS_OFF (2*STG_F)            // after 2 stages
#define ATT_SMEM_FLOATS (PS_OFF + 8*16*68)
#define ATT_SMEM (ATT_SMEM_FLOATS * sizeof(float))   // 106496 B

__global__ __launch_bounds__(256, 2)
void attn_mma_kernel(const float* __restrict__ qkv, const float* __restrict__ mask,
                     float* __restrict__ att)
{
    extern __shared__ float smf[];
    const uint32_t smb = smem_u32(smf);

    const int t    = threadIdx.x;
    const int lane = t & 31;
    const int wid  = t >> 5;
    const int g    = lane >> 2;
    const int t4   = lane & 3;
    const int bh   = blockIdx.y;
    const int b    = bh / HEADS;
    const int h    = bh % HEADS;
    const int q0   = blockIdx.x * 128;

    float* Ps = smf + PS_OFF + wid * (16 * 68);
    const int qrow = wid * 16 + g;

    // fill mapping: thread t -> row t>>2; 16-float column group (t&3)*16
    const int frow = t >> 2;
    const int fseg = (t & 3) * 16;

    const float* kvsrc = qkv + ((size_t)(b * SEQ)) * QKV_N + h * (3 * HD);

    auto load_tile = [&](int kt, int s) {
        const float* src = kvsrc + (size_t)(kt * 64 + frow) * QKV_N;
        const uint32_t kdst = smb + (uint32_t)(s * STG_F + frow * KP + fseg) * 4u;
        const uint32_t vdst = smb + (uint32_t)(s * STG_F + KV_K + frow * VP + fseg) * 4u;
#pragma unroll
        for (int i = 0; i < 4; i++) {
            cp_async16(kdst + i * 16u, src + HD + fseg + i * 4);      // K
            cp_async16(vdst + i * 16u, src + 2 * HD + fseg + i * 4);  // V
        }
    };

    // in-place tf32 conversion of the 32 floats this thread copied
    auto convert_tile = [&](int s) {
        float* kp = smf + s * STG_F + frow * KP + fseg;
        float* vp = smf + s * STG_F + KV_K + frow * VP + fseg;
#pragma unroll
        for (int i = 0; i < 4; i++) {
            float4 a = *(float4*)(kp + i * 4);
            a.x = f2tf32(a.x); a.y = f2tf32(a.y); a.z = f2tf32(a.z); a.w = f2tf32(a.w);
            *(float4*)(kp + i * 4) = a;
            float4 c = *(float4*)(vp + i * 4);
            c.x = f2tf32(c.x); c.y = f2tf32(c.y); c.z = f2tf32(c.z); c.w = f2tf32(c.w);
            *(float4*)(vp + i * 4) = c;
        }
    };

    // ---- Q fragments -> registers (once); thread covers rows qrow, qrow+8 ----
    uint32_t qf[8][4];
    {
        const float* q0p = qkv + (size_t)(b * SEQ + q0 + qrow) * QKV_N + h * (3 * HD);
        const float* q1p = q0p + 8 * QKV_N;
#pragma unroll
        for (int kk8 = 0; kk8 < 8; kk8++) {
            int d0 = kk8 * 8 + t4;
            qf[kk8][0] = tf32bits(q0p[d0] * 0.125f);
            qf[kk8][1] = tf32bits(q1p[d0] * 0.125f);
            qf[kk8][2] = tf32bits(q0p[d0 + 4] * 0.125f);
            qf[kk8][3] = tf32bits(q1p[d0 + 4] * 0.125f);
        }
    }

    float m0 = -1e30f, m1 = -1e30f, l0 = 0.f, l1 = 0.f;
    float acc[8][4];
#pragma unroll
    for (int ni = 0; ni < 8; ni++)
#pragma unroll
        for (int r = 0; r < 4; r++) acc[ni][r] = 0.f;

    load_tile(0, 0);
    cp_commit();

    const int NT = SEQ / 64;
    for (int kt = 0; kt < NT; kt++) {
        const int s = kt & 1;
        cp_wait0();
        __syncthreads();   // tile kt landed; all warps done with stage s^1 reads

        if (kt + 1 < NT) { load_tile(kt + 1, s ^ 1); cp_commit(); }

        convert_tile(s);
        __syncthreads();   // converted values visible to all warps

        const float* Ks = smf + s * STG_F;
        const float* Vs = Ks + KV_K;

        // ---- scores = Q @ K^T ----
        float sc[8][4];
#pragma unroll
        for (int ni = 0; ni < 8; ni++)
#pragma unroll
            for (int r = 0; r < 4; r++) sc[ni][r] = 0.f;

#pragma unroll
        for (int kk8 = 0; kk8 < 8; kk8++) {
            const int kk = kk8 * 8;
#pragma unroll
            for (int ni = 0; ni < 8; ni++) {
                uint32_t bf[2];
                bf[0] = __float_as_uint(Ks[(ni * 8 + g) * KP + kk + t4]);
                bf[1] = __float_as_uint(Ks[(ni * 8 + g) * KP + kk + t4 + 4]);
                mma_tf32(sc[ni], qf[kk8], bf);
            }
        }

        // ---- + mask, online softmax (rows qrow, qrow+8) ----
        {
            const int k0 = kt * 64;
            const float* mr0 = mask + (size_t)(q0 + qrow) * SEQ + k0 + 2 * t4;
            const float* mr1 = mr0 + 8 * SEQ;
            float mx0 = -1e30f, mx1 = -1e30f;
#pragma unroll
            for (int ni = 0; ni < 8; ni++) {
                float2 a = *(const float2*)(mr0 + 8 * ni);
                float2 c = *(const float2*)(mr1 + 8 * ni);
                sc[ni][0] += a.x; sc[ni][1] += a.y;
                sc[ni][2] += c.x; sc[ni][3] += c.y;
                mx0 = fmaxf(mx0, fmaxf(sc[ni][0], sc[ni][1]));
                mx1 = fmaxf(mx1, fmaxf(sc[ni][2], sc[ni][3]));
            }
#pragma unroll
            for (int off = 1; off <= 2; off <<= 1) {
                mx0 = fmaxf(mx0, __shfl_xor_sync(0xffffffffu, mx0, off));
                mx1 = fmaxf(mx1, __shfl_xor_sync(0xffffffffu, mx1, off));
            }
            float mn0 = fmaxf(m0, mx0), mn1 = fmaxf(m1, mx1);
            float c0 = __expf(m0 - mn0), c1 = __expf(m1 - mn1);
            float rs0 = 0.f, rs1 = 0.f;
            float* p0 = Ps + g * 68 + 2 * t4;
            float* p1 = Ps + (g + 8) * 68 + 2 * t4;
#pragma unroll
            for (int ni = 0; ni < 8; ni++) {
                float e00 = f2tf32(__expf(sc[ni][0] - mn0));
                float e01 = f2tf32(__expf(sc[ni][1] - mn0));
                float e10 = f2tf32(__expf(sc[ni][2] - mn1));
                float e11 = f2tf32(__expf(sc[ni][3] - mn1));
                rs0 += e00 + e01; rs1 += e10 + e11;
                *(float2*)(p0 + 8 * ni) = make_float2(e00, e01);
                *(float2*)(p1 + 8 * ni) = make_float2(e10, e11);
            }
#pragma unroll
            for (int off = 1; off <= 2; off <<= 1) {
                rs0 += __shfl_xor_sync(0xffffffffu, rs0, off);
                rs1 += __shfl_xor_sync(0xffffffffu, rs1, off);
            }
            l0 = l0 * c0 + rs0; l1 = l1 * c1 + rs1;
            m0 = mn0; m1 = mn1;
#pragma unroll
            for (int ni = 0; ni < 8; ni++) {
                acc[ni][0] *= c0; acc[ni][1] *= c0;
                acc[ni][2] *= c1; acc[ni][3] *= c1;
            }
        }
        __syncwarp();

        // ---- acc += P @ V  (A from Ps; B = Vs[key][d], pitch 72 conflict-free) ----
#pragma unroll
        for (int kk8 = 0; kk8 < 8; kk8++) {
            const int kk = kk8 * 8;
            uint32_t af[4];
            af[0] = __float_as_uint(Ps[g * 68 + kk + t4]);
            af[1] = __float_as_uint(Ps[(g + 8) * 68 + kk + t4]);
            af[2] = __float_as_uint(Ps[g * 68 + kk + t4 + 4]);
            af[3] = __float_as_uint(Ps[(g + 8) * 68 + kk + t4 + 4]);
#pragma unroll
            for (int ni = 0; ni < 8; ni++) {
                uint32_t bf[2];
                bf[0] = __float_as_uint(Vs[(kk + t4) * VP + ni * 8 + g]);
                bf[1] = __float_as_uint(Vs[(kk + t4 + 4) * VP + ni * 8 + g]);
                mma_tf32(acc[ni], af, bf);
            }
        }
    }

    // ---- normalize + store ----
    {
        float inv0 = 1.f / l0, inv1 = 1.f / l1;
        float* o0 = att + (size_t)(b * SEQ + q0 + qrow) * DMODEL + h * HD + 2 * t4;
        float* o1 = o0 + 8 * DMODEL;
#pragma unroll
        for (int ni = 0; ni < 8; ni++) {
            *(float2*)(o0 + 8 * ni) = make_float2(acc[ni][0] * inv0, acc[ni][1] * inv0);
            *(float2*)(o1 + 8 * ni) = make_float2(acc[ni][2] * inv1, acc[ni][3] * inv1);
        }
    }
}

// ---------------------------------------------------------------------------
extern "C" void kernel_launch(void* const* d_in, const int* in_sizes, int n_in,
                              void* d_out, int out_size)
{
    const float* x     = (const float*)d_in[0];
    const float* mask  = (const float*)d_in[1];
    const float* w_qkv = (const float*)d_in[2];
    const float* b_qkv = (const float*)d_in[3];
    const float* w_out = (const float*)d_in[4];
    const float* b_out = (const float*)d_in[5];
    float* out = (float*)d_out;

    float* qkv; cudaGetSymbolAddress((void**)&qkv, g_qkv);
    float* att; cudaGetSymbolAddress((void**)&att, g_att);

    cudaFuncSetAttribute(gemm_mma_kernel, cudaFuncAttributeMaxDynamicSharedMemorySize,
                         (int)GEMM_SMEM);
    cudaFuncSetAttribute(attn_mma_kernel, cudaFuncAttributeMaxDynamicSharedMemorySize,
                         (int)ATT_SMEM);

    // 1) QKV projection (tf32 mma + cp.async pipeline)
    {
        dim3 grid(QKV_N / 128, MROWS / 128);
        gemm_mma_kernel<<<grid, 256, GEMM_SMEM>>>(x, w_qkv, b_qkv, qkv, QKV_N, DMODEL);
    }
    // 2) attention (tf32 mma flash, cp.async K/V + in-smem cvt, Q-in-regs)
    {
        dim3 grid(SEQ / 128, BATCH * HEADS);
        attn_mma_kernel<<<grid, 256, ATT_SMEM>>>(qkv, mask, att);
    }
    // 3) output projection (tf32 mma + cp.async pipeline)
    {
        dim3 grid(DMODEL / 128, MROWS / 128);
        gemm_mma_kernel<<<grid, 256, GEMM_SMEM>>>(att, w_out, b_out, out, DMODEL, DMODEL);
    }
}

// round 10
// speedup vs baseline: 1.0828x; 1.0828x over previous
#include <cuda_runtime.h>
#include <math.h>
#include <stdint.h>

#define BATCH 2
#define SEQ   2048
#define DMODEL 1024
#define HEADS 16
#define HD    64
#define QKV_N (3*DMODEL)       // 3072
#define MROWS (BATCH*SEQ)      // 4096

__device__ float g_qkv[(size_t)MROWS * QKV_N];     // [B*S, 3072] (tf32-rounded)
__device__ float g_att[(size_t)MROWS * DMODEL];    // [B*S, 1024] (tf32-rounded)
__device__ float g_xr[(size_t)MROWS * DMODEL];     // rounded x
__device__ float g_wqkvr[(size_t)DMODEL * QKV_N];  // rounded w_qkv
__device__ float g_woutr[(size_t)DMODEL * DMODEL]; // rounded w_out

// ===========================================================================
// helpers
// ===========================================================================
__device__ __forceinline__ float f2tf32(float f) {
    uint32_t r;
    asm("cvt.rna.tf32.f32 %0, %1;" : "=r"(r) : "f"(f));
    return __uint_as_float(r);
}
__device__ __forceinline__ uint32_t smem_u32(const void* p) {
    uint32_t a;
    asm("{ .reg .u64 t; cvta.to.shared.u64 t, %1; cvt.u32.u64 %0, t; }" : "=r"(a) : "l"(p));
    return a;
}
__device__ __forceinline__ void mma_tf32(float c[4], const uint32_t a[4], const uint32_t b[2]) {
    asm volatile(
        "mma.sync.aligned.m16n8k8.row.col.f32.tf32.tf32.f32 "
        "{%0,%1,%2,%3}, {%4,%5,%6,%7}, {%8,%9}, {%0,%1,%2,%3};"
        : "+f"(c[0]), "+f"(c[1]), "+f"(c[2]), "+f"(c[3])
        : "r"(a[0]), "r"(a[1]), "r"(a[2]), "r"(a[3]), "r"(b[0]), "r"(b[1]));
}
__device__ __forceinline__ void cp_async16(uint32_t saddr, const void* gptr) {
    asm volatile("cp.async.ca.shared.global [%0], [%1], 16;" :: "r"(saddr), "l"(gptr));
}
__device__ __forceinline__ void cp_commit() {
    asm volatile("cp.async.commit_group;" ::: "memory");
}
__device__ __forceinline__ void cp_wait2() {
    asm volatile("cp.async.wait_group 2;" ::: "memory");
}

// ===========================================================================
// elementwise tf32 rounding pass (streaming)
// ===========================================================================
__global__ __launch_bounds__(256)
void round_tf32_kernel(const float* __restrict__ src, float* __restrict__ dst, int n4)
{
    int i = blockIdx.x * blockDim.x + threadIdx.x;
    if (i < n4) {
        float4 v = ((const float4*)src)[i];
        v.x = f2tf32(v.x); v.y = f2tf32(v.y); v.z = f2tf32(v.z); v.w = f2tf32(v.w);
        ((float4*)dst)[i] = v;
    }
}

// ===========================================================================
// tf32 mma.sync GEMM + bias, 4-stage cp.async pipeline.
// Operands are PRE-ROUNDED tf32 values -> no cvt in the inner loop.
// RND: round the output (for qkv, consumed by attention as tf32 anyway).
// ===========================================================================
#define AS_P 20
#define BS_P 136
#define AS_FLOATS (128 * AS_P)
#define BS_FLOATS (16 * BS_P)
#define ST_FLOATS (AS_FLOATS + BS_FLOATS)
#define NSTAGE 4
#define GEMM_SMEM (NSTAGE * ST_FLOATS * sizeof(float))   // 75776

template <bool RND>
__global__ __launch_bounds__(256, 2)
void gemm_mma_kernel(const float* __restrict__ A, const float* __restrict__ W,
                     const float* __restrict__ bias, float* __restrict__ C,
                     int N, int K)
{
    extern __shared__ float smf[];
    const uint32_t smb = smem_u32(smf);

    const int t    = threadIdx.x;
    const int lane = t & 31;
    const int wid  = t >> 5;
    const int wm   = (wid >> 2) * 64;
    const int wn   = (wid & 3) * 32;
    const int g    = lane >> 2;
    const int t4   = lane & 3;
    const int m0   = blockIdx.y * 128;
    const int n0   = blockIdx.x * 128;

    const int ar = t >> 1;
    const int as0 = (t & 1) * 2;
    const int br = t >> 4;
    const int bs0 = (t & 15) * 2;

    float acc[4][4][4];
#pragma unroll
    for (int mi = 0; mi < 4; mi++)
#pragma unroll
        for (int ni = 0; ni < 4; ni++)
#pragma unroll
            for (int r = 0; r < 4; r++) acc[mi][ni][r] = 0.f;

    const int nch = K / 16;

    auto load_chunk = [&](int c, int s) {
        const uint32_t stA = smb + (uint32_t)(s * ST_FLOATS) * 4u;
        const uint32_t stB = stA + (uint32_t)AS_FLOATS * 4u;
        const float* Ab = A + (size_t)(m0 + ar) * K + c * 16 + as0 * 4;
        cp_async16(stA + (uint32_t)(ar * AS_P + as0 * 4) * 4u, Ab);
        cp_async16(stA + (uint32_t)(ar * AS_P + (as0 + 1) * 4) * 4u, Ab + 4);
        const float* Wb = W + (size_t)(c * 16 + br) * N + n0 + bs0 * 4;
        cp_async16(stB + (uint32_t)(br * BS_P + bs0 * 4) * 4u, Wb);
        cp_async16(stB + (uint32_t)(br * BS_P + (bs0 + 1) * 4) * 4u, Wb + 4);
    };

#pragma unroll
    for (int c = 0; c < NSTAGE - 1; c++) { load_chunk(c, c); cp_commit(); }

    for (int c = 0; c < nch; c++) {
        cp_wait2();
        __syncthreads();

        if (c + NSTAGE - 1 < nch) load_chunk(c + NSTAGE - 1, (c + NSTAGE - 1) & (NSTAGE - 1));
        cp_commit();

        const int s = c & (NSTAGE - 1);
        const float* as_ = smf + s * ST_FLOATS;
        const float* bs_ = as_ + AS_FLOATS;

#pragma unroll
        for (int ks = 0; ks < 2; ks++) {
            const int kk = ks * 8;
            uint32_t af[4][4], bf[4][2];
#pragma unroll
            for (int mi = 0; mi < 4; mi++) {
                int r0 = wm + mi * 16 + g;
                af[mi][0] = __float_as_uint(as_[r0 * AS_P + kk + t4]);
                af[mi][1] = __float_as_uint(as_[(r0 + 8) * AS_P + kk + t4]);
                af[mi][2] = __float_as_uint(as_[r0 * AS_P + kk + t4 + 4]);
                af[mi][3] = __float_as_uint(as_[(r0 + 8) * AS_P + kk + t4 + 4]);
            }
#pragma unroll
            for (int ni = 0; ni < 4; ni++) {
                int cc = wn + ni * 8 + g;
                bf[ni][0] = __float_as_uint(bs_[(kk + t4) * BS_P + cc]);
                bf[ni][1] = __float_as_uint(bs_[(kk + t4 + 4) * BS_P + cc]);
            }
#pragma unroll
            for (int mi = 0; mi < 4; mi++)
#pragma unroll
                for (int ni = 0; ni < 4; ni++)
                    mma_tf32(acc[mi][ni], af[mi], bf[ni]);
        }
    }

#pragma unroll
    for (int mi = 0; mi < 4; mi++) {
        int row = m0 + wm + mi * 16 + g;
#pragma unroll
        for (int ni = 0; ni < 4; ni++) {
            int col = n0 + wn + ni * 8 + 2 * t4;
            float2 bv = *(const float2*)(bias + col);
            float2 v0, v1;
            if (RND) {
                v0 = make_float2(f2tf32(acc[mi][ni][0] + bv.x), f2tf32(acc[mi][ni][1] + bv.y));
                v1 = make_float2(f2tf32(acc[mi][ni][2] + bv.x), f2tf32(acc[mi][ni][3] + bv.y));
            } else {
                v0 = make_float2(acc[mi][ni][0] + bv.x, acc[mi][ni][1] + bv.y);
                v1 = make_float2(acc[mi][ni][2] + bv.x, acc[mi][ni][3] + bv.y);
            }
            *(float2*)(C + (size_t)row * N + col)       = v0;
            *(float2*)(C + (size_t)(row + 8) * N + col) = v1;
        }
    }
}

// ===========================================================================
// tf32 mma.sync flash attention — R6-exact structure (430us measured);
// qkv is pre-rounded so all load-time cvts are gone.
// ===========================================================================
#define QS_OFF 0                    // [128][68]
#define KS_OFF (128*68)             // [64][68]
#define VT_OFF (KS_OFF + 64*68)     // [64][68]  Vt[d][key]
#define PS_OFF (VT_OFF + 64*68)     // 8 x [16][68]
#define ATT_SMEM_FLOATS (PS_OFF + 8*16*68)
#define ATT_SMEM (ATT_SMEM_FLOATS * sizeof(float))   // 104448 B

__global__ __launch_bounds__(256, 2)
void attn_mma_kernel(const float* __restrict__ qkv, const float* __restrict__ mask,
                     float* __restrict__ att)
{
    extern __shared__ float smf[];
    float* Qs = smf + QS_OFF;
    float* Ks = smf + KS_OFF;
    float* Vt = smf + VT_OFF;

    const int t    = threadIdx.x;
    const int lane = t & 31;
    const int wid  = t >> 5;
    const int g    = lane >> 2;
    const int t4   = lane & 3;
    const int bh   = blockIdx.y;
    const int b    = bh / HEADS;
    const int h    = bh % HEADS;
    const int q0   = blockIdx.x * 128;

    float* Ps = smf + PS_OFF + wid * (16 * 68);

    // ---- load Q tile [128][64], fold 1/8 scale (exact; values pre-rounded) ----
    {
        const float* qb = qkv + ((size_t)(b * SEQ + q0)) * QKV_N + h * (3 * HD);
#pragma unroll
        for (int i = 0; i < 8; i++) {
            int idx = t + i * 256;
            int row = idx >> 4, seg = idx & 15;
            float4 v = *(const float4*)(qb + (size_t)row * QKV_N + seg * 4);
            float* d = Qs + row * 68 + seg * 4;
            d[0] = v.x * 0.125f; d[1] = v.y * 0.125f;
            d[2] = v.z * 0.125f; d[3] = v.w * 0.125f;
        }
    }

    float m0 = -1e30f, m1 = -1e30f, l0 = 0.f, l1 = 0.f;
    float acc[8][4];
#pragma unroll
    for (int ni = 0; ni < 8; ni++)
#pragma unroll
        for (int r = 0; r < 4; r++) acc[ni][r] = 0.f;

    const int qrow = wid * 16 + g;
    const float* qsw = Qs + qrow * 68;

    for (int kt = 0; kt < SEQ / 64; kt++) {
        const int k0 = kt * 64;
        __syncthreads();

        {
            const float* kb = qkv + ((size_t)(b * SEQ + k0)) * QKV_N + h * (3 * HD) + HD;
#pragma unroll
            for (int i = 0; i < 4; i++) {
                int idx = t + i * 256;
                int row = idx >> 4, seg = idx & 15;
                float4 v = *(const float4*)(kb + (size_t)row * QKV_N + seg * 4);
                *(float4*)(Ks + row * 68 + seg * 4) = v;
            }
        }
        {
            const int kg = t >> 4, ds = t & 15;
            const float* vb = qkv + ((size_t)(b * SEQ + k0 + kg * 4)) * QKV_N
                            + h * (3 * HD) + 2 * HD + ds * 4;
            float4 r0 = *(const float4*)(vb);
            float4 r1 = *(const float4*)(vb + QKV_N);
            float4 r2 = *(const float4*)(vb + 2 * QKV_N);
            float4 r3 = *(const float4*)(vb + 3 * QKV_N);
            *(float4*)(Vt + (ds * 4 + 0) * 68 + kg * 4) = make_float4(r0.x, r1.x, r2.x, r3.x);
            *(float4*)(Vt + (ds * 4 + 1) * 68 + kg * 4) = make_float4(r0.y, r1.y, r2.y, r3.y);
            *(float4*)(Vt + (ds * 4 + 2) * 68 + kg * 4) = make_float4(r0.z, r1.z, r2.z, r3.z);
            *(float4*)(Vt + (ds * 4 + 3) * 68 + kg * 4) = make_float4(r0.w, r1.w, r2.w, r3.w);
        }
        __syncthreads();

        float sc[8][4];
#pragma unroll
        for (int ni = 0; ni < 8; ni++)
#pragma unroll
            for (int r = 0; r < 4; r++) sc[ni][r] = 0.f;

#pragma unroll
        for (int kk = 0; kk < 64; kk += 8) {
            uint32_t af[4];
            af[0] = __float_as_uint(qsw[kk + t4]);
            af[1] = __float_as_uint(qsw[8 * 68 + kk + t4]);
            af[2] = __float_as_uint(qsw[kk + t4 + 4]);
            af[3] = __float_as_uint(qsw[8 * 68 + kk + t4 + 4]);
#pragma unroll
            for (int ni = 0; ni < 8; ni++) {
                uint32_t bf[2];
                bf[0] = __float_as_uint(Ks[(ni * 8 + g) * 68 + kk + t4]);
                bf[1] = __float_as_uint(Ks[(ni * 8 + g) * 68 + kk + t4 + 4]);
                mma_tf32(sc[ni], af, bf);
            }
        }

        {
            const float* mr0 = mask + (size_t)(q0 + qrow) * SEQ + k0 + 2 * t4;
            const float* mr1 = mr0 + 8 * SEQ;
            float mx0 = -1e30f, mx1 = -1e30f;
#pragma unroll
            for (int ni = 0; ni < 8; ni++) {
                float2 a = *(const float2*)(mr0 + 8 * ni);
                float2 c = *(const float2*)(mr1 + 8 * ni);
                sc[ni][0] += a.x; sc[ni][1] += a.y;
                sc[ni][2] += c.x; sc[ni][3] += c.y;
                mx0 = fmaxf(mx0, fmaxf(sc[ni][0], sc[ni][1]));
                mx1 = fmaxf(mx1, fmaxf(sc[ni][2], sc[ni][3]));
            }
#pragma unroll
            for (int off = 1; off <= 2; off <<= 1) {
                mx0 = fmaxf(mx0, __shfl_xor_sync(0xffffffffu, mx0, off));
                mx1 = fmaxf(mx1, __shfl_xor_sync(0xffffffffu, mx1, off));
            }
            float mn0 = fmaxf(m0, mx0), mn1 = fmaxf(m1, mx1);
            float c0 = __expf(m0 - mn0), c1 = __expf(m1 - mn1);
            float rs0 = 0.f, rs1 = 0.f;
            float* p0 = Ps + g * 68 + 2 * t4;
            float* p1 = Ps + (g + 8) * 68 + 2 * t4;
#pragma unroll
            for (int ni = 0; ni < 8; ni++) {
                float e00 = f2tf32(__expf(sc[ni][0] - mn0));
                float e01 = f2tf32(__expf(sc[ni][1] - mn0));
                float e10 = f2tf32(__expf(sc[ni][2] - mn1));
                float e11 = f2tf32(__expf(sc[ni][3] - mn1));
                rs0 += e00 + e01; rs1 += e10 + e11;
                *(float2*)(p0 + 8 * ni) = make_float2(e00, e01);
                *(float2*)(p1 + 8 * ni) = make_float2(e10, e11);
            }
#pragma unroll
            for (int off = 1; off <= 2; off <<= 1) {
                rs0 += __shfl_xor_sync(0xffffffffu, rs0, off);
                rs1 += __shfl_xor_sync(0xffffffffu, rs1, off);
            }
            l0 = l0 * c0 + rs0; l1 = l1 * c1 + rs1;
            m0 = mn0; m1 = mn1;
#pragma unroll
            for (int ni = 0; ni < 8; ni++) {
                acc[ni][0] *= c0; acc[ni][1] *= c0;
                acc[ni][2] *= c1; acc[ni][3] *= c1;
            }
        }
        __syncwarp();

#pragma unroll
        for (int kk = 0; kk < 64; kk += 8) {
            uint32_t af[4];
            af[0] = __float_as_uint(Ps[g * 68 + kk + t4]);
            af[1] = __float_as_uint(Ps[(g + 8) * 68 + kk + t4]);
            af[2] = __float_as_uint(Ps[g * 68 + kk + t4 + 4]);
            af[3] = __float_as_uint(Ps[(g + 8) * 68 + kk + t4 + 4]);
#pragma unroll
            for (int ni = 0; ni < 8; ni++) {
                uint32_t bf[2];
                bf[0] = __float_as_uint(Vt[(ni * 8 + g) * 68 + kk + t4]);
                bf[1] = __float_as_uint(Vt[(ni * 8 + g) * 68 + kk + t4 + 4]);
                mma_tf32(acc[ni], af, bf);
            }
        }
    }

    // ---- normalize + store, tf32-rounded (out-proj consumes it as tf32) ----
    {
        float inv0 = 1.f / l0, inv1 = 1.f / l1;
        float* o0 = att + (size_t)(b * SEQ + q0 + qrow) * DMODEL + h * HD + 2 * t4;
        float* o1 = o0 + 8 * DMODEL;
#pragma unroll
        for (int ni = 0; ni < 8; ni++) {
            *(float2*)(o0 + 8 * ni) = make_float2(f2tf32(acc[ni][0] * inv0),
                                                  f2tf32(acc[ni][1] * inv0));
            *(float2*)(o1 + 8 * ni) = make_float2(f2tf32(acc[ni][2] * inv1),
                                                  f2tf32(acc[ni][3] * inv1));
        }
    }
}

// ---------------------------------------------------------------------------
extern "C" void kernel_launch(void* const* d_in, const int* in_sizes, int n_in,
                              void* d_out, int out_size)
{
    const float* x     = (const float*)d_in[0];
    const float* mask  = (const float*)d_in[1];
    const float* w_qkv = (const float*)d_in[2];
    const float* b_qkv = (const float*)d_in[3];
    const float* w_out = (const float*)d_in[4];
    const float* b_out = (const float*)d_in[5];
    float* out = (float*)d_out;

    float* qkv;   cudaGetSymbolAddress((void**)&qkv,   g_qkv);
    float* att;   cudaGetSymbolAddress((void**)&att,   g_att);
    float* xr;    cudaGetSymbolAddress((void**)&xr,    g_xr);
    float* wqkvr; cudaGetSymbolAddress((void**)&wqkvr, g_wqkvr);
    float* woutr; cudaGetSymbolAddress((void**)&woutr, g_woutr);

    cudaFuncSetAttribute(gemm_mma_kernel<true>, cudaFuncAttributeMaxDynamicSharedMemorySize,
                         (int)GEMM_SMEM);
    cudaFuncSetAttribute(gemm_mma_kernel<false>, cudaFuncAttributeMaxDynamicSharedMemorySize,
                         (int)GEMM_SMEM);
    cudaFuncSetAttribute(attn_mma_kernel, cudaFuncAttributeMaxDynamicSharedMemorySize,
                         (int)ATT_SMEM);

    // 0) pre-round operands to tf32 (streaming, ~15us total)
    round_tf32_kernel<<<(MROWS * DMODEL / 4 + 255) / 256, 256>>>(x, xr, MROWS * DMODEL / 4);
    round_tf32_kernel<<<(DMODEL * QKV_N / 4 + 255) / 256, 256>>>(w_qkv, wqkvr, DMODEL * QKV_N / 4);
    round_tf32_kernel<<<(DMODEL * DMODEL / 4 + 255) / 256, 256>>>(w_out, woutr, DMODEL * DMODEL / 4);

    // 1) QKV projection (cvt-free inner loop; rounded output)
    {
        dim3 grid(QKV_N / 128, MROWS / 128);
        gemm_mma_kernel<true><<<grid, 256, GEMM_SMEM>>>(xr, wqkvr, b_qkv, qkv, QKV_N, DMODEL);
    }
    // 2) attention (R6 structure; cvt-free loads)
    {
        dim3 grid(SEQ / 128, BATCH * HEADS);
        attn_mma_kernel<<<grid, 256, ATT_SMEM>>>(qkv, mask, att);
    }
    // 3) output projection (cvt-free inner loop; fp32 output)
    {
        dim3 grid(DMODEL / 128, MROWS / 128);
        gemm_mma_kernel<false><<<grid, 256, GEMM_SMEM>>>(att, woutr, b_out, out, DMODEL, DMODEL);
    }
}